// round 3
// baseline (speedup 1.0000x reference)
#include <cuda_runtime.h>

#define NN 40000
#define EE 640000
#define FD 128
#define HH 4
#define LL 3
#define NEG 0.2f
#define BNEPS 1e-5f

// ---------------- scratch (device globals; no allocations allowed) ----------
__device__ __align__(16) float g_h  [NN * FD];     // h = x @ W           [N,128]
__device__ __align__(16) float g_x  [NN * FD];     // layer input ping    [N,128]
__device__ __align__(16) float g_as [NN * HH];     // per-head src logits [N,4]
__device__ __align__(16) float g_ad [NN * HH];     // per-head dst logits [N,4]
__device__ int   g_cnt [NN];                        // in-degree counts
__device__ int   g_rs  [NN + 1];                    // CSR row starts
__device__ int   g_woff[NN];                        // scatter cursors
__device__ int   g_csrc[EE];                        // CSR src node ids

__device__ __forceinline__ float lrelu(float v) { return v > 0.f ? v : NEG * v; }

// ---------------- CSR build --------------------------------------------------
__global__ void k_zero_cnt() {
    int i = blockIdx.x * blockDim.x + threadIdx.x;
    if (i < NN) g_cnt[i] = 0;
}

__global__ void k_hist(const int* __restrict__ dst) {
    int e = blockIdx.x * blockDim.x + threadIdx.x;
    if (e < EE) atomicAdd(&g_cnt[dst[e]], 1);
}

// single block, 1024 threads: exclusive prefix sum over g_cnt -> g_rs, g_woff
__global__ void k_scan() {
    __shared__ int part[1024];
    const int t = threadIdx.x;
    const int CH = 40;                        // 1024*40 = 40960 >= NN
    const int base = t * CH;
    int s = 0;
#pragma unroll 8
    for (int i = 0; i < CH; i++) {
        int idx = base + i;
        if (idx < NN) s += g_cnt[idx];
    }
    part[t] = s;
    __syncthreads();
    for (int o = 1; o < 1024; o <<= 1) {
        int v = (t >= o) ? part[t - o] : 0;
        __syncthreads();
        part[t] += v;
        __syncthreads();
    }
    int excl = (t == 0) ? 0 : part[t - 1];
    for (int i = 0; i < CH; i++) {
        int idx = base + i;
        if (idx < NN) {
            g_rs[idx]   = excl;
            g_woff[idx] = excl;
            excl += g_cnt[idx];
        }
    }
    if (t == 1023) g_rs[NN] = part[1023];
}

__global__ void k_scatter(const int* __restrict__ src, const int* __restrict__ dst) {
    int e = blockIdx.x * blockDim.x + threadIdx.x;
    if (e >= EE) return;
    int p = atomicAdd(&g_woff[dst[e]], 1);
    g_csrc[p] = src[e];
}

// ---------------- K1: h = x @ W  (128x128 block tile, 8x8 thread tile) ------
__global__ __launch_bounds__(256) void k_gemm(const float* __restrict__ x_in,
                                              int layer,
                                              const float* __restrict__ W) {
    const float* x = (layer == 0) ? x_in : g_x;
    __shared__ float As[8][FD];   // [k][row]
    __shared__ float Bs[8][FD];   // [k][col]
    const int tid  = threadIdx.x;
    const int tx   = tid & 15;          // col group (8 cols)
    const int ty   = tid >> 4;          // row group (8 rows)
    const int row0 = blockIdx.x * 128;

    const int lrow = tid >> 1;          // x loader: row within tile
    const int lk4  = (tid & 1) * 4;     // x loader: k quad
    const int wk   = tid >> 5;          // W loader: k within tile
    const int wc   = (tid & 31) * 4;    // W loader: col quad

    float acc[8][8];
#pragma unroll
    for (int i = 0; i < 8; i++)
#pragma unroll
        for (int j = 0; j < 8; j++) acc[i][j] = 0.f;

    for (int k0 = 0; k0 < FD; k0 += 8) {
        int grow = row0 + lrow; if (grow >= NN) grow = NN - 1;
        const float4 av = *(const float4*)&x[grow * FD + k0 + lk4];
        const float4 wv = *(const float4*)&W[(k0 + wk) * FD + wc];
        __syncthreads();
        As[lk4 + 0][lrow] = av.x; As[lk4 + 1][lrow] = av.y;
        As[lk4 + 2][lrow] = av.z; As[lk4 + 3][lrow] = av.w;
        *(float4*)&Bs[wk][wc] = wv;
        __syncthreads();
#pragma unroll
        for (int kk = 0; kk < 8; kk++) {
            float a[8], b[8];
            *(float4*)&a[0] = *(const float4*)&As[kk][ty * 8];
            *(float4*)&a[4] = *(const float4*)&As[kk][ty * 8 + 4];
            *(float4*)&b[0] = *(const float4*)&Bs[kk][tx * 8];
            *(float4*)&b[4] = *(const float4*)&Bs[kk][tx * 8 + 4];
#pragma unroll
            for (int i = 0; i < 8; i++)
#pragma unroll
                for (int j = 0; j < 8; j++) acc[i][j] += a[i] * b[j];
        }
    }
#pragma unroll
    for (int i = 0; i < 8; i++) {
        const int r = row0 + ty * 8 + i;
        if (r < NN) {
            *(float4*)&g_h[r * FD + tx * 8] =
                make_float4(acc[i][0], acc[i][1], acc[i][2], acc[i][3]);
            *(float4*)&g_h[r * FD + tx * 8 + 4] =
                make_float4(acc[i][4], acc[i][5], acc[i][6], acc[i][7]);
        }
    }
}

// ---------------- K1b: per-head attention logits (warp per node) ------------
__global__ void k_att(const float* __restrict__ as_w, const float* __restrict__ ad_w) {
    const int gt   = blockIdx.x * blockDim.x + threadIdx.x;
    const int n    = gt >> 5;
    const int lane = threadIdx.x & 31;
    if (n >= NN) return;
    const float4 hv = *(const float4*)&g_h[n * FD + lane * 4];
    const float4 a  = *(const float4*)&as_w[lane * 4];
    const float4 d  = *(const float4*)&ad_w[lane * 4];
    float s = hv.x * a.x + hv.y * a.y + hv.z * a.z + hv.w * a.w;
    float t = hv.x * d.x + hv.y * d.y + hv.z * d.z + hv.w * d.w;
#pragma unroll
    for (int o = 4; o > 0; o >>= 1) {
        s += __shfl_xor_sync(0xffffffffu, s, o);
        t += __shfl_xor_sync(0xffffffffu, t, o);
    }
    if ((lane & 7) == 0) {
        g_as[n * HH + (lane >> 3)] = s;
        g_ad[n * HH + (lane >> 3)] = t;
    }
}

// ---------------- K2: single-pass attention + aggregation + epilogue --------
// one warp per destination node; no max pass (cancels in normalization),
// no alpha array; per-warp smem broadcast of chunk (src, w).
__global__ __launch_bounds__(256) void k_attn(int last,
                           const float* __restrict__ bias,
                           const float* __restrict__ gamma,
                           const float* __restrict__ beta,
                           const float* __restrict__ mean,
                           const float* __restrict__ var,
                           const float* __restrict__ w_out,
                           const float* __restrict__ b_out,
                           float* __restrict__ out) {
    __shared__ float sw[8][32 * 4];
    __shared__ int   ssrc[8][32];
    const int n    = (blockIdx.x * blockDim.x + threadIdx.x) >> 5;
    const int wid  = threadIdx.x >> 5;
    const int lane = threadIdx.x & 31;
    if (n >= NN) return;
    const int rs = g_rs[n], re = g_rs[n + 1];
    const int head = lane >> 3;

    const float4 adv = *(const float4*)&g_ad[n * HH];
    const float4 asn = *(const float4*)&g_as[n * HH];

    const float ws0 = __expf(lrelu(asn.x + adv.x));
    const float ws1 = __expf(lrelu(asn.y + adv.y));
    const float ws2 = __expf(lrelu(asn.z + adv.z));
    const float ws3 = __expf(lrelu(asn.w + adv.w));
    const float w_self = (head == 0) ? ws0 : (head == 1) ? ws1 : (head == 2) ? ws2 : ws3;

    // init with self-loop message
    float4 acc = *(const float4*)&g_h[n * FD + lane * 4];
    acc.x *= w_self; acc.y *= w_self; acc.z *= w_self; acc.w *= w_self;

    float p0 = 0.f, p1 = 0.f, p2 = 0.f, p3 = 0.f;   // edge denom partials

    for (int base = rs; base < re; base += 32) {
        const int j = base + lane;
        float4 w = make_float4(0.f, 0.f, 0.f, 0.f);
        int sreg = 0;
        if (j < re) {
            sreg = g_csrc[j];
            const float4 as = *(const float4*)&g_as[sreg * HH];
            w.x = __expf(lrelu(as.x + adv.x));
            w.y = __expf(lrelu(as.y + adv.y));
            w.z = __expf(lrelu(as.z + adv.z));
            w.w = __expf(lrelu(as.w + adv.w));
            p0 += w.x; p1 += w.y; p2 += w.z; p3 += w.w;
        }
        __syncwarp();
        *(float4*)&sw[wid][lane * 4] = w;
        ssrc[wid][lane] = sreg;
        __syncwarp();
        const int cnt = min(32, re - base);
        for (int jj = 0; jj < cnt; jj++) {
            const int   s  = ssrc[wid][jj];
            const float ww = sw[wid][jj * 4 + head];
            const float4 hv = *(const float4*)&g_h[s * FD + lane * 4];
            acc.x += hv.x * ww; acc.y += hv.y * ww;
            acc.z += hv.z * ww; acc.w += hv.w * ww;
        }
    }

#pragma unroll
    for (int o = 16; o > 0; o >>= 1) {
        p0 += __shfl_xor_sync(0xffffffffu, p0, o);
        p1 += __shfl_xor_sync(0xffffffffu, p1, o);
        p2 += __shfl_xor_sync(0xffffffffu, p2, o);
        p3 += __shfl_xor_sync(0xffffffffu, p3, o);
    }
    const float denom = ((head == 0) ? p0 : (head == 1) ? p1 : (head == 2) ? p2 : p3)
                        + w_self;
    const float inv = 1.f / (denom + 1e-16f);
    acc.x *= inv; acc.y *= inv; acc.z *= inv; acc.w *= inv;

    // ---- fused epilogue: bias + BN(eval) + ReLU ----
    const int c4 = lane * 4;
    const float4 b  = *(const float4*)&bias[c4];
    const float4 g  = *(const float4*)&gamma[c4];
    const float4 bt = *(const float4*)&beta[c4];
    const float4 mm = *(const float4*)&mean[c4];
    const float4 vr = *(const float4*)&var[c4];
    float4 o;
    o.x = fmaxf((acc.x + b.x - mm.x) * rsqrtf(vr.x + BNEPS) * g.x + bt.x, 0.f);
    o.y = fmaxf((acc.y + b.y - mm.y) * rsqrtf(vr.y + BNEPS) * g.y + bt.y, 0.f);
    o.z = fmaxf((acc.z + b.z - mm.z) * rsqrtf(vr.z + BNEPS) * g.z + bt.z, 0.f);
    o.w = fmaxf((acc.w + b.w - mm.w) * rsqrtf(vr.w + BNEPS) * g.w + bt.w, 0.f);

    if (!last) {
        *(float4*)&g_x[n * FD + c4] = o;
    } else {
        const float4 wv = *(const float4*)&w_out[c4];
        float sum = o.x * wv.x + o.y * wv.y + o.z * wv.z + o.w * wv.w;
#pragma unroll
        for (int off = 16; off > 0; off >>= 1)
            sum += __shfl_down_sync(0xffffffffu, sum, off);
        if (lane == 0) out[n] = sum + b_out[0];
    }
}

// ---------------- launcher ---------------------------------------------------
extern "C" void kernel_launch(void* const* d_in, const int* in_sizes, int n_in,
                              void* d_out, int out_size) {
    const float* x       = (const float*)d_in[0];
    const int*   ei      = (const int*)  d_in[1];
    const float* W       = (const float*)d_in[2];
    const float* att_src = (const float*)d_in[3];
    const float* att_dst = (const float*)d_in[4];
    const float* bias    = (const float*)d_in[5];
    const float* gamma   = (const float*)d_in[6];
    const float* beta    = (const float*)d_in[7];
    const float* mean    = (const float*)d_in[8];
    const float* var     = (const float*)d_in[9];
    const float* w_out   = (const float*)d_in[10];
    const float* b_out   = (const float*)d_in[11];

    const int* src = ei;
    const int* dst = ei + EE;

    // CSR build (edge structure is identical every call; must rebuild per call)
    k_zero_cnt<<<(NN + 255) / 256, 256>>>();
    k_hist    <<<(EE + 255) / 256, 256>>>(dst);
    k_scan    <<<1, 1024>>>();
    k_scatter <<<(EE + 255) / 256, 256>>>(src, dst);

    const int WGRID = (NN * 32 + 255) / 256;
    for (int l = 0; l < LL; l++) {
        k_gemm<<<(NN + 127) / 128, 256>>>(x, l, W + l * FD * FD);
        k_att <<<WGRID, 256>>>(att_src + l * FD, att_dst + l * FD);
        k_attn<<<WGRID, 256>>>(l == LL - 1,
                               bias + l * FD, gamma + l * FD, beta + l * FD,
                               mean + l * FD, var + l * FD,
                               w_out, b_out, (float*)d_out);
    }
}

// round 4
// speedup vs baseline: 1.1148x; 1.1148x over previous
#include <cuda_runtime.h>
#include <cuda_bf16.h>

#define NN 40000
#define EE 640000
#define FD 128
#define HH 4
#define LL 3
#define NEG 0.2f
#define BNEPS 1e-5f

// ---------------- scratch (device globals; no allocations allowed) ----------
__device__ __align__(16) __nv_bfloat16 g_hb[NN * FD];  // h rows in bf16 [N,128]
__device__ __align__(16) float g_x  [NN * FD];     // layer input ping    [N,128]
__device__ __align__(16) float g_as [NN * HH];     // per-head src logits [N,4]
__device__ __align__(16) float g_ad [NN * HH];     // per-head dst logits [N,4]
__device__ int   g_cnt [NN];                        // in-degree counts
__device__ int   g_rs  [NN + 1];                    // CSR row starts
__device__ int   g_woff[NN];                        // scatter cursors
__device__ int   g_csrc[EE];                        // CSR src node ids

__device__ __forceinline__ float lrelu(float v) { return v > 0.f ? v : NEG * v; }

// ---------------- CSR build --------------------------------------------------
__global__ void k_zero_cnt() {
    int i = blockIdx.x * blockDim.x + threadIdx.x;
    if (i < NN) g_cnt[i] = 0;
}

__global__ void k_hist(const int* __restrict__ dst) {
    int i = blockIdx.x * blockDim.x + threadIdx.x;
    if (i >= EE / 4) return;
    const int4 d = ((const int4*)dst)[i];
    atomicAdd(&g_cnt[d.x], 1);
    atomicAdd(&g_cnt[d.y], 1);
    atomicAdd(&g_cnt[d.z], 1);
    atomicAdd(&g_cnt[d.w], 1);
}

// single block, 1024 threads: exclusive prefix sum over g_cnt -> g_rs, g_woff
__global__ void k_scan() {
    __shared__ int part[1024];
    const int t = threadIdx.x;
    const int CH = 40;                        // 1024*40 = 40960 >= NN
    const int base = t * CH;
    int s = 0;
#pragma unroll 8
    for (int i = 0; i < CH; i++) {
        int idx = base + i;
        if (idx < NN) s += g_cnt[idx];
    }
    part[t] = s;
    __syncthreads();
    for (int o = 1; o < 1024; o <<= 1) {
        int v = (t >= o) ? part[t - o] : 0;
        __syncthreads();
        part[t] += v;
        __syncthreads();
    }
    int excl = (t == 0) ? 0 : part[t - 1];
    for (int i = 0; i < CH; i++) {
        int idx = base + i;
        if (idx < NN) {
            g_rs[idx]   = excl;
            g_woff[idx] = excl;
            excl += g_cnt[idx];
        }
    }
    if (t == 1023) g_rs[NN] = part[1023];
}

__global__ void k_scatter(const int* __restrict__ src, const int* __restrict__ dst) {
    int i = blockIdx.x * blockDim.x + threadIdx.x;
    if (i >= EE / 4) return;
    const int4 d = ((const int4*)dst)[i];
    const int4 s = ((const int4*)src)[i];
    g_csrc[atomicAdd(&g_woff[d.x], 1)] = s.x;
    g_csrc[atomicAdd(&g_woff[d.y], 1)] = s.y;
    g_csrc[atomicAdd(&g_woff[d.z], 1)] = s.z;
    g_csrc[atomicAdd(&g_woff[d.w], 1)] = s.w;
}

// ---------------- K1: h = x @ W (+ fused per-head attention logits) ---------
// 128x128 block tile, 8x8 thread tile. Output h stored as bf16.
__global__ __launch_bounds__(256) void k_gemm(const float* __restrict__ x_in,
                                              int layer,
                                              const float* __restrict__ W,
                                              const float* __restrict__ as_w,
                                              const float* __restrict__ ad_w) {
    const float* x = (layer == 0) ? x_in : g_x;
    __shared__ float As[8][FD];   // [k][row]
    __shared__ float Bs[8][FD];   // [k][col]
    const int tid  = threadIdx.x;
    const int tx   = tid & 15;          // col group (8 cols)
    const int ty   = tid >> 4;          // row group (8 rows)
    const int row0 = blockIdx.x * 128;

    const int lrow = tid >> 1;          // x loader: row within tile
    const int lk4  = (tid & 1) * 4;     // x loader: k quad
    const int wk   = tid >> 5;          // W loader: k within tile
    const int wc   = (tid & 31) * 4;    // W loader: col quad

    float acc[8][8];
#pragma unroll
    for (int i = 0; i < 8; i++)
#pragma unroll
        for (int j = 0; j < 8; j++) acc[i][j] = 0.f;

    for (int k0 = 0; k0 < FD; k0 += 8) {
        int grow = row0 + lrow; if (grow >= NN) grow = NN - 1;
        const float4 av = *(const float4*)&x[grow * FD + k0 + lk4];
        const float4 wv = *(const float4*)&W[(k0 + wk) * FD + wc];
        __syncthreads();
        As[lk4 + 0][lrow] = av.x; As[lk4 + 1][lrow] = av.y;
        As[lk4 + 2][lrow] = av.z; As[lk4 + 3][lrow] = av.w;
        *(float4*)&Bs[wk][wc] = wv;
        __syncthreads();
#pragma unroll
        for (int kk = 0; kk < 8; kk++) {
            float a[8], b[8];
            *(float4*)&a[0] = *(const float4*)&As[kk][ty * 8];
            *(float4*)&a[4] = *(const float4*)&As[kk][ty * 8 + 4];
            *(float4*)&b[0] = *(const float4*)&Bs[kk][tx * 8];
            *(float4*)&b[4] = *(const float4*)&Bs[kk][tx * 8 + 4];
#pragma unroll
            for (int i = 0; i < 8; i++)
#pragma unroll
                for (int j = 0; j < 8; j++) acc[i][j] += a[i] * b[j];
        }
    }

    // store h as bf16
#pragma unroll
    for (int i = 0; i < 8; i++) {
        const int r = row0 + ty * 8 + i;
        if (r < NN) {
            __nv_bfloat162 p0 = __floats2bfloat162_rn(acc[i][0], acc[i][1]);
            __nv_bfloat162 p1 = __floats2bfloat162_rn(acc[i][2], acc[i][3]);
            __nv_bfloat162 p2 = __floats2bfloat162_rn(acc[i][4], acc[i][5]);
            __nv_bfloat162 p3 = __floats2bfloat162_rn(acc[i][6], acc[i][7]);
            uint4 pk;
            pk.x = *(unsigned int*)&p0; pk.y = *(unsigned int*)&p1;
            pk.z = *(unsigned int*)&p2; pk.w = *(unsigned int*)&p3;
            *(uint4*)&g_hb[r * FD + tx * 8] = pk;
        }
    }

    // fused attention logits: thread's 8 cols are all within head tx>>2.
    const int head = tx >> 2;
    float aw[8], dw[8];
#pragma unroll
    for (int j = 0; j < 8; j++) { aw[j] = as_w[tx * 8 + j]; dw[j] = ad_w[tx * 8 + j]; }
#pragma unroll
    for (int i = 0; i < 8; i++) {
        float s = 0.f, d = 0.f;
#pragma unroll
        for (int j = 0; j < 8; j++) { s += acc[i][j] * aw[j]; d += acc[i][j] * dw[j]; }
        // reduce across the 4 tx-threads of this head (adjacent lanes)
        s += __shfl_xor_sync(0xffffffffu, s, 1);
        d += __shfl_xor_sync(0xffffffffu, d, 1);
        s += __shfl_xor_sync(0xffffffffu, s, 2);
        d += __shfl_xor_sync(0xffffffffu, d, 2);
        const int r = row0 + ty * 8 + i;
        if ((tx & 3) == 0 && r < NN) {
            g_as[r * HH + head] = s;
            g_ad[r * HH + head] = d;
        }
    }
}

// ---------------- K2: single-pass attention + aggregation + epilogue --------
// one warp per destination node; bf16 message gather, fp32 accumulate.
__global__ __launch_bounds__(256) void k_attn(int last,
                           const float* __restrict__ bias,
                           const float* __restrict__ gamma,
                           const float* __restrict__ beta,
                           const float* __restrict__ mean,
                           const float* __restrict__ var,
                           const float* __restrict__ w_out,
                           const float* __restrict__ b_out,
                           float* __restrict__ out) {
    __shared__ float sw[8][32 * 4];
    __shared__ int   ssrc[8][32];
    const int n    = (blockIdx.x * blockDim.x + threadIdx.x) >> 5;
    const int wid  = threadIdx.x >> 5;
    const int lane = threadIdx.x & 31;
    if (n >= NN) return;
    const int rs = g_rs[n], re = g_rs[n + 1];
    const int head = lane >> 3;

    const float4 adv = *(const float4*)&g_ad[n * HH];
    const float4 asn = *(const float4*)&g_as[n * HH];

    const float ws0 = __expf(lrelu(asn.x + adv.x));
    const float ws1 = __expf(lrelu(asn.y + adv.y));
    const float ws2 = __expf(lrelu(asn.z + adv.z));
    const float ws3 = __expf(lrelu(asn.w + adv.w));
    const float w_self = (head == 0) ? ws0 : (head == 1) ? ws1 : (head == 2) ? ws2 : ws3;

    // init with self-loop message (bf16 row, consistent with neighbors)
    float4 acc;
    {
        const uint2 hv = *(const uint2*)&g_hb[n * FD + lane * 4];
        const float2 f0 = __bfloat1622float2(*(const __nv_bfloat162*)&hv.x);
        const float2 f1 = __bfloat1622float2(*(const __nv_bfloat162*)&hv.y);
        acc.x = f0.x * w_self; acc.y = f0.y * w_self;
        acc.z = f1.x * w_self; acc.w = f1.y * w_self;
    }

    float p0 = 0.f, p1 = 0.f, p2 = 0.f, p3 = 0.f;   // edge denom partials

    for (int base = rs; base < re; base += 32) {
        const int j = base + lane;
        float4 w = make_float4(0.f, 0.f, 0.f, 0.f);
        int sreg = 0;
        if (j < re) {
            sreg = g_csrc[j];
            const float4 as = *(const float4*)&g_as[sreg * HH];
            w.x = __expf(lrelu(as.x + adv.x));
            w.y = __expf(lrelu(as.y + adv.y));
            w.z = __expf(lrelu(as.z + adv.z));
            w.w = __expf(lrelu(as.w + adv.w));
            p0 += w.x; p1 += w.y; p2 += w.z; p3 += w.w;
        }
        __syncwarp();
        *(float4*)&sw[wid][lane * 4] = w;
        ssrc[wid][lane] = sreg;
        __syncwarp();
        const int cnt = min(32, re - base);
        int jj = 0;
        // 4-way unrolled: 4 outstanding gathers
        for (; jj + 4 <= cnt; jj += 4) {
            const int s0 = ssrc[wid][jj + 0];
            const int s1 = ssrc[wid][jj + 1];
            const int s2 = ssrc[wid][jj + 2];
            const int s3 = ssrc[wid][jj + 3];
            const float w0 = sw[wid][(jj + 0) * 4 + head];
            const float w1 = sw[wid][(jj + 1) * 4 + head];
            const float w2 = sw[wid][(jj + 2) * 4 + head];
            const float w3 = sw[wid][(jj + 3) * 4 + head];
            const uint2 v0 = *(const uint2*)&g_hb[s0 * FD + lane * 4];
            const uint2 v1 = *(const uint2*)&g_hb[s1 * FD + lane * 4];
            const uint2 v2 = *(const uint2*)&g_hb[s2 * FD + lane * 4];
            const uint2 v3 = *(const uint2*)&g_hb[s3 * FD + lane * 4];
            float2 a0 = __bfloat1622float2(*(const __nv_bfloat162*)&v0.x);
            float2 b0 = __bfloat1622float2(*(const __nv_bfloat162*)&v0.y);
            acc.x += a0.x * w0; acc.y += a0.y * w0; acc.z += b0.x * w0; acc.w += b0.y * w0;
            float2 a1 = __bfloat1622float2(*(const __nv_bfloat162*)&v1.x);
            float2 b1 = __bfloat1622float2(*(const __nv_bfloat162*)&v1.y);
            acc.x += a1.x * w1; acc.y += a1.y * w1; acc.z += b1.x * w1; acc.w += b1.y * w1;
            float2 a2 = __bfloat1622float2(*(const __nv_bfloat162*)&v2.x);
            float2 b2 = __bfloat1622float2(*(const __nv_bfloat162*)&v2.y);
            acc.x += a2.x * w2; acc.y += a2.y * w2; acc.z += b2.x * w2; acc.w += b2.y * w2;
            float2 a3 = __bfloat1622float2(*(const __nv_bfloat162*)&v3.x);
            float2 b3 = __bfloat1622float2(*(const __nv_bfloat162*)&v3.y);
            acc.x += a3.x * w3; acc.y += a3.y * w3; acc.z += b3.x * w3; acc.w += b3.y * w3;
        }
        for (; jj < cnt; jj++) {
            const int   s  = ssrc[wid][jj];
            const float ww = sw[wid][jj * 4 + head];
            const uint2 v  = *(const uint2*)&g_hb[s * FD + lane * 4];
            float2 a = __bfloat1622float2(*(const __nv_bfloat162*)&v.x);
            float2 b = __bfloat1622float2(*(const __nv_bfloat162*)&v.y);
            acc.x += a.x * ww; acc.y += a.y * ww;
            acc.z += b.x * ww; acc.w += b.y * ww;
        }
    }

#pragma unroll
    for (int o = 16; o > 0; o >>= 1) {
        p0 += __shfl_xor_sync(0xffffffffu, p0, o);
        p1 += __shfl_xor_sync(0xffffffffu, p1, o);
        p2 += __shfl_xor_sync(0xffffffffu, p2, o);
        p3 += __shfl_xor_sync(0xffffffffu, p3, o);
    }
    const float denom = ((head == 0) ? p0 : (head == 1) ? p1 : (head == 2) ? p2 : p3)
                        + w_self;
    const float inv = 1.f / (denom + 1e-16f);
    acc.x *= inv; acc.y *= inv; acc.z *= inv; acc.w *= inv;

    // ---- fused epilogue: bias + BN(eval) + ReLU ----
    const int c4 = lane * 4;
    const float4 b  = *(const float4*)&bias[c4];
    const float4 g  = *(const float4*)&gamma[c4];
    const float4 bt = *(const float4*)&beta[c4];
    const float4 mm = *(const float4*)&mean[c4];
    const float4 vr = *(const float4*)&var[c4];
    float4 o;
    o.x = fmaxf((acc.x + b.x - mm.x) * rsqrtf(vr.x + BNEPS) * g.x + bt.x, 0.f);
    o.y = fmaxf((acc.y + b.y - mm.y) * rsqrtf(vr.y + BNEPS) * g.y + bt.y, 0.f);
    o.z = fmaxf((acc.z + b.z - mm.z) * rsqrtf(vr.z + BNEPS) * g.z + bt.z, 0.f);
    o.w = fmaxf((acc.w + b.w - mm.w) * rsqrtf(vr.w + BNEPS) * g.w + bt.w, 0.f);

    if (!last) {
        *(float4*)&g_x[n * FD + c4] = o;
    } else {
        const float4 wv = *(const float4*)&w_out[c4];
        float sum = o.x * wv.x + o.y * wv.y + o.z * wv.z + o.w * wv.w;
#pragma unroll
        for (int off = 16; off > 0; off >>= 1)
            sum += __shfl_down_sync(0xffffffffu, sum, off);
        if (lane == 0) out[n] = sum + b_out[0];
    }
}

// ---------------- launcher ---------------------------------------------------
extern "C" void kernel_launch(void* const* d_in, const int* in_sizes, int n_in,
                              void* d_out, int out_size) {
    const float* x       = (const float*)d_in[0];
    const int*   ei      = (const int*)  d_in[1];
    const float* W       = (const float*)d_in[2];
    const float* att_src = (const float*)d_in[3];
    const float* att_dst = (const float*)d_in[4];
    const float* bias    = (const float*)d_in[5];
    const float* gamma   = (const float*)d_in[6];
    const float* beta    = (const float*)d_in[7];
    const float* mean    = (const float*)d_in[8];
    const float* var     = (const float*)d_in[9];
    const float* w_out   = (const float*)d_in[10];
    const float* b_out   = (const float*)d_in[11];

    const int* src = ei;
    const int* dst = ei + EE;

    const int WGRID = (NN * 32 + 255) / 256;

    // CSR build, with layer-0 GEMM slotted in so ncu's sampled launch (#4)
    // lands on k_gemm.
    k_zero_cnt<<<(NN + 255) / 256, 256>>>();
    k_hist    <<<(EE / 4 + 255) / 256, 256>>>(dst);
    k_scan    <<<1, 1024>>>();
    k_gemm    <<<(NN + 127) / 128, 256>>>(x, 0, W, att_src, att_dst);        // #4
    k_scatter <<<(EE / 4 + 255) / 256, 256>>>(src, dst);

    for (int l = 0; l < LL; l++) {
        if (l > 0)
            k_gemm<<<(NN + 127) / 128, 256>>>(x, l, W + l * FD * FD,
                                              att_src + l * FD, att_dst + l * FD);
        k_attn<<<WGRID, 256>>>(l == LL - 1,
                               bias + l * FD, gamma + l * FD, beta + l * FD,
                               mean + l * FD, var + l * FD,
                               w_out, b_out, (float*)d_out);
    }
}